// round 14
// baseline (speedup 1.0000x reference)
#include <cuda_runtime.h>
#include <cuda_bf16.h>
#include <math.h>

#define B_ 8
#define NPT 16384
#define SPT 1024
#define NS 64
#define DD 64
#define C0 67
#define MTOT (B_*SPT*NS)      // 524288
#define NGRP (MTOT/NS)        // 8192
#define RR2 0.09f
#define EPSV 1e-5f

typedef unsigned long long ull;
typedef unsigned uint;

// ---------------- scratch (static device globals; no allocation) -------------
__device__ __align__(16) float g_ptsT[(size_t)B_*NPT*DD];       // 33.5 MB
__device__ __align__(16) float4 g_pk[(size_t)B_*NPT];           // 2 MB packed xyz+id
__device__ float g_newxyz[B_*SPT*3];
__device__ int   g_fpsidx[B_*SPT];
__device__ int   g_newptr[B_*SPT];
__device__ int   g_gid[B_*SPT*NS];
__device__ __align__(16) float g_y1[(size_t)MTOT*128];          // 268 MB
__device__ __align__(16) float g_y2[(size_t)MTOT*128];          // 268 MB
__device__ __align__(16) float g_mx[(size_t)NGRP*256];          // 8 MB
__device__ __align__(16) float g_mn[(size_t)NGRP*256];          // 8 MB
__device__ float g_sum[3*256];
__device__ float g_sqs[3*256];
// weights: bf16 hi/lo INTERLEAVED in m16n8k16 B-fragment layout:
// per (ksg, nb, lane): 4 words [bh_reg0, bh_reg1, bl_reg0, bl_reg1]
#define W0PAIRS (5*1024)      // KP=80: 5 ksteps (pair-entries)
#define W1PAIRS (8*1024)      // KP=128
#define W2PAIRS (2*8*1024)    // 2 otiles
#define TOTALW (W0PAIRS + W1PAIRS + W2PAIRS)
__device__ __align__(16) uint g_wf0[2*W0PAIRS];
__device__ __align__(16) uint g_wf1[2*W1PAIRS];
__device__ __align__(16) uint g_wf2[2*W2PAIRS];

// ---------------- f32x2 packed helpers ---------------------------------------
#define ADD2(o, a, b) asm("add.rn.f32x2 %0, %1, %2;" : "=l"(o) : "l"(a), "l"(b))
#define MUL2(o, a, b) asm("mul.rn.f32x2 %0, %1, %2;" : "=l"(o) : "l"(a), "l"(b))
#define FMA2(o, a, b, c) asm("fma.rn.f32x2 %0, %1, %2, %3;" : "=l"(o) : "l"(a), "l"(b), "l"(c))

__device__ __forceinline__ ull bcast2(float v) {
    unsigned u = __float_as_uint(v);
    return ((ull)u << 32) | (ull)u;
}
__device__ __forceinline__ float lo2(ull m) { return __uint_as_float((unsigned)m); }
__device__ __forceinline__ float hi2(ull m) { return __uint_as_float((unsigned)(m >> 32)); }

__device__ __forceinline__ uint pk_bf2(float a, float b) {
    uint r;
    asm("cvt.rn.bf16x2.f32 %0, %1, %2;" : "=r"(r) : "f"(b), "f"(a));
    return r;
}
__device__ __forceinline__ void split2(float v0, float v1, uint& wh, uint& wl) {
    wh = pk_bf2(v0, v1);
    __nv_bfloat162 h2 = *(__nv_bfloat162*)&wh;
    float h0 = __bfloat162float(h2.x), h1 = __bfloat162float(h2.y);
    wl = pk_bf2(v0 - h0, v1 - h1);
}

// BN finalize formula (gemm preamble + final_out); bit-identical both places
__device__ __forceinline__ void bn_coef(int layer, int c,
                                        const float* __restrict__ gamma,
                                        const float* __restrict__ beta,
                                        float& s, float& sh) {
    const float invM = 1.f / (float)MTOT;
    float mu  = g_sum[layer*256 + c] * invM;
    float var = g_sqs[layer*256 + c] * invM - mu*mu;
    if (var < 0.f) var = 0.f;
    s  = gamma[c] * rsqrtf(var + EPSV);
    sh = fmaf(-mu, s, beta[c]);
}

// store float4 (row r in 0..63, chunk-local col base = c4*4) into A frag smem
__device__ __forceinline__ void frag_store4(uint* Ah, uint* Al, int r, int c4, float4 v) {
    int r16 = r & 15, mb = r >> 4;
    int kk0 = (c4*4) & 15, kst = (c4*4) >> 4;
    int reg = (r16 >> 3) + ((kk0 >> 3) << 1);
    int l0  = ((r16 & 7) << 2) | ((kk0 >> 1) & 3);
    int i0  = ((kst*4 + mb)*32 + l0)*4 + reg;
    uint wh, wl;
    split2(v.x, v.y, wh, wl);
    Ah[i0] = wh; Al[i0] = wl;
    split2(v.z, v.w, wh, wl);
    Ah[i0 + 4] = wh; Al[i0 + 4] = wl;
}

// ---------------- FRONT: fps (blocks 0..7) + prep/transpose (blocks 8+) ------
#define FPS_SMEM ((3*NPT + 64) * 4)
#define NTRB 4096
__global__ void __launch_bounds__(512, 1)
front_kernel(const float* __restrict__ xyz, const int* __restrict__ idx,
             const float* __restrict__ pts,
             const float* __restrict__ w0, const float* __restrict__ w1,
             const float* __restrict__ w2,
             float* __restrict__ out_xyz) {
    extern __shared__ float fsm[];
    const int t = threadIdx.x;

    if (blockIdx.x >= 8) {
        int bid = blockIdx.x - 8;
        int gi = bid*512 + t;
        if (gi < 768) { g_sum[gi] = 0.f; g_sqs[gi] = 0.f; }
        if (gi < B_*NPT) {
            int b = gi >> 14, n = gi & (NPT-1);
            const float* px = xyz + (size_t)b*3*NPT;
            g_pk[gi] = make_float4(px[n], px[NPT+n], px[2*NPT+n], __int_as_float(idx[gi]));
        }
        if (gi < TOTALW) {
            int layer, j, otile = 0;
            if (gi < W0PAIRS) { layer = 0; j = gi; }
            else if (gi < W0PAIRS + W1PAIRS) { layer = 1; j = gi - W0PAIRS; }
            else { layer = 2; j = gi - W0PAIRS - W1PAIRS; otile = j >> 13; j &= 8191; }
            int reg = j & 1, ln = (j >> 1) & 31, nb = (j >> 6) & 15, ksg = j >> 10;
            int o  = otile*128 + nb*8 + (ln >> 2);
            int c0 = ksg*16 + reg*8 + (ln & 3)*2;
            float v0, v1;
            if (layer == 0) {
                int s0 = (c0   < 64) ? (c0   + 3) : (c0   - 64);
                int s1 = (c0+1 < 64) ? (c0+1 + 3) : (c0+1 - 64);
                v0 = (c0   < C0) ? w0[o*C0 + s0] : 0.f;
                v1 = (c0+1 < C0) ? w0[o*C0 + s1] : 0.f;
            } else if (layer == 1) {
                v0 = w1[o*128 + c0]; v1 = w1[o*128 + c0 + 1];
            } else {
                v0 = w2[o*128 + c0]; v1 = w2[o*128 + c0 + 1];
            }
            uint wh, wl;
            split2(v0, v1, wh, wl);
            // interleaved: q*4 + {reg: hi, 2+reg: lo}
            int q = (ksg*16 + nb)*32 + ln;
            int hidx = q*4 + reg, lidx = q*4 + 2 + reg;
            if (layer == 0)      { g_wf0[hidx] = wh; g_wf0[lidx] = wl; }
            else if (layer == 1) { g_wf1[hidx] = wh; g_wf1[lidx] = wl; }
            else { int off = otile*16384; g_wf2[off + hidx] = wh; g_wf2[off + lidx] = wl; }
        }
        int tile_id = bid*2 + (t >> 8);
        int sub = t & 255, tx = sub & 31, ty = sub >> 5;   // 32 x 8
        int bx = tile_id & 511, byz = tile_id >> 9;
        int by = byz & 1, bz = byz >> 1;
        int n0 = bx * 32, c0 = by * 32;
        float* tb = fsm + (t >> 8) * 1088;
        #pragma unroll
        for (int j = 0; j < 32; j += 8)
            tb[(ty + j)*33 + tx] = pts[((size_t)bz*DD + c0 + ty + j)*NPT + n0 + tx];
        __syncthreads();
        #pragma unroll
        for (int j = 0; j < 32; j += 8)
            g_ptsT[((size_t)bz*NPT + n0 + ty + j)*DD + c0 + tx] = tb[tx*33 + ty + j];
        return;
    }

    // ===================== FPS role =====================
    float* sx = fsm;
    float* sy = sx + NPT;
    float* sz = sy + NPT;
    float* redv = sz + NPT;
    __shared__ int s_idx[2];

    const int b = blockIdx.x;
    const float* px = xyz + (size_t)b*3*NPT;
    const float* py = px + NPT;
    const float* pz = py + NPT;

    for (int n = t; n < NPT; n += 512) { sx[n]=px[n]; sy[n]=py[n]; sz[n]=pz[n]; }
    if (t == 0) s_idx[0] = 0;
    __syncthreads();

    ull xp[16], yp[16];
    float dist[32];
    #pragma unroll
    for (int i = 0; i < 16; i++) {
        int p = t + (i << 9);
        xp[i] = *(const ull*)&sx[2*p];
        yp[i] = *(const ull*)&sy[2*p];
        dist[2*i] = 1e10f; dist[2*i+1] = 1e10f;
    }

    const int lane = t & 31;
    for (int s = 0; s < SPT; s++) {
        int far = s_idx[s & 1];
        float cx = sx[far], cy = sy[far], cz = sz[far];
        if (t == 0) {
            g_fpsidx[b*SPT + s] = far;
            g_newptr[b*SPT + s] = idx[b*NPT + far];
            g_newxyz[(b*SPT + s)*3 + 0] = cx;
            g_newxyz[(b*SPT + s)*3 + 1] = cy;
            g_newxyz[(b*SPT + s)*3 + 2] = cz;
            out_xyz[(b*3 + 0)*SPT + s] = cx;
            out_xyz[(b*3 + 1)*SPT + s] = cy;
            out_xyz[(b*3 + 2)*SPT + s] = cz;
            s_idx[(s + 1) & 1] = 0x7fffffff;
        }
        if (s == SPT - 1) break;

        ull ncx = bcast2(-cx), ncy = bcast2(-cy), ncz = bcast2(-cz);
        float best = -1.f;
        #pragma unroll
        for (int i = 0; i < 16; i++) {
            int p = t + (i << 9);
            ull z2 = *(const ull*)&sz[2*p];
            ull dx2, dy2, dz2, m;
            ADD2(dx2, xp[i], ncx);
            ADD2(dy2, yp[i], ncy);
            ADD2(dz2, z2,    ncz);
            MUL2(m, dx2, dx2);
            FMA2(m, dy2, dy2, m);
            FMA2(m, dz2, dz2, m);
            float d0 = fminf(dist[2*i],   lo2(m));
            float d1 = fminf(dist[2*i+1], hi2(m));
            dist[2*i] = d0; dist[2*i+1] = d1;
            best = fmaxf(best, d0);
            best = fmaxf(best, d1);
        }
        float wmax = best;
        #pragma unroll
        for (int o = 16; o > 0; o >>= 1)
            wmax = fmaxf(wmax, __shfl_xor_sync(0xffffffffu, wmax, o));
        if (lane == 0) redv[t >> 5] = wmax;
        __syncthreads();
        float vmax = redv[lane & 15];
        #pragma unroll
        for (int o = 8; o > 0; o >>= 1)
            vmax = fmaxf(vmax, __shfl_xor_sync(0xffffffffu, vmax, o));
        if (best == vmax) {
            int found = 0x7fffffff;
            #pragma unroll
            for (int i = 0; i < 16; i++) {
                int p2 = 2*(t + (i << 9));
                if (dist[2*i]   == vmax) found = min(found, p2);
                if (dist[2*i+1] == vmax) found = min(found, p2 + 1);
            }
            atomicMin(&s_idx[(s + 1) & 1], found);
        }
        __syncthreads();
    }
}

// ---------------- ball query: one warp per (b,s), packed float4 --------------
__global__ void __launch_bounds__(256)
ballquery_kernel() {
    int warp = (blockIdx.x * blockDim.x + threadIdx.x) >> 5;
    int lane = threadIdx.x & 31;
    if (warp >= B_*SPT) return;
    int b = warp / SPT;
    float cx = g_newxyz[warp*3+0], cy = g_newxyz[warp*3+1], cz = g_newxyz[warp*3+2];
    int np = g_newptr[warp];
    float cn = cx*cx + cy*cy + cz*cz;
    const float4* pk = g_pk + (size_t)b*NPT;
    int* gout = g_gid + (size_t)warp*NS;

    int cnt = 0, first = -1;
    for (int n0 = 0; n0 < NPT && cnt < NS; n0 += 128) {
        float4 vv[4];
        #pragma unroll
        for (int sb = 0; sb < 4; sb++) vv[sb] = pk[n0 + sb*32 + lane];
        #pragma unroll
        for (int sb = 0; sb < 4; sb++) {
            int n = n0 + sb*32 + lane;
            float x = vv[sb].x, y = vv[sb].y, z = vv[sb].z;
            float pn = x*x + y*y + z*z;
            float sq = cn + pn - 2.f*(cx*x + cy*y + cz*z);
            bool hit = !(sq > RR2) && (__float_as_int(vv[sb].w) == np);
            unsigned m = __ballot_sync(0xffffffffu, hit);
            if (m) {
                if (first < 0) first = n0 + sb*32 + __ffs(m) - 1;
                int pos = cnt + __popc(m & ((1u << lane) - 1));
                if (hit && pos < NS) gout[pos] = n;
                cnt += __popc(m);
                if (cnt > NS) cnt = NS;
            }
        }
    }
    if (first < 0) { first = g_fpsidx[warp]; }
    if (cnt == 0) { if (lane == 0) gout[0] = first; cnt = 1; }
    for (int p = cnt + lane; p < NS; p += 32) gout[p] = first;
}

// ---------------- bf16 mma helpers -------------------------------------------
#define MMAB(d, a, b) asm volatile( \
    "mma.sync.aligned.m16n8k16.row.col.f32.bf16.bf16.f32 " \
    "{%0,%1,%2,%3},{%4,%5,%6,%7},{%8,%9},{%0,%1,%2,%3};\n" \
    : "+f"(d[0]), "+f"(d[1]), "+f"(d[2]), "+f"(d[3]) \
    : "r"(a[0]), "r"(a[1]), "r"(a[2]), "r"(a[3]), "r"(b[0]), "r"(b[1]))

// ---------------- one K-chunk (CTA tile 64x128, 128 threads) -----------------
template<int KS16, int LAYER>
__device__ __forceinline__ void do_chunk(
    const float* __restrict__ A, const float* __restrict__ xyz, size_t m0, int kc,
    const float* sc, const float* sh,
    const uint* __restrict__ Wf, int wfbase,
    uint* Ah, uint* Al, uint* Bc,
    int t, int lane, int w, int wc, float acc[2][8][4])
{
    constexpr int KP = 128;
    constexpr int CW = KS16 * 4;

    if (LAYER == 0) {
        const int bb = (int)(m0 >> 16);
        if (KS16 == 4) {
            for (int i = t; i < 64*16; i += 128) {
                int r = i >> 4, c4 = i & 15;
                int g = g_gid[m0 + r];
                float4 v = *(const float4*)&g_ptsT[((size_t)bb*NPT + g)*DD + c4*4];
                frag_store4(Ah, Al, r, c4, v);
            }
        } else {
            const float* px = xyz + (size_t)bb*3*NPT;
            for (int i = t; i < 64*4; i += 128) {
                int r = i >> 2, c4 = i & 3;
                float4 v = make_float4(0.f, 0.f, 0.f, 0.f);
                if (c4 == 0) {
                    int g = g_gid[m0 + r];
                    int bs = (int)((m0 + r) >> 6);
                    v = make_float4(px[g]        - g_newxyz[bs*3+0],
                                    px[NPT+g]    - g_newxyz[bs*3+1],
                                    px[2*NPT+g]  - g_newxyz[bs*3+2], 0.f);
                }
                frag_store4(Ah, Al, r, c4, v);
            }
        }
    } else {
        for (int i = t; i < 64*CW; i += 128) {
            int r = i / CW, c4 = i - r*CW;
            float4 v = *(const float4*)&A[(m0 + r)*KP + kc + c4*4];
            int ch = kc + c4*4;
            v.x = fmaxf(0.f, fmaf(sc[ch+0], v.x, sh[ch+0]));
            v.y = fmaxf(0.f, fmaf(sc[ch+1], v.y, sh[ch+1]));
            v.z = fmaxf(0.f, fmaf(sc[ch+2], v.z, sh[ch+2]));
            v.w = fmaxf(0.f, fmaf(sc[ch+3], v.w, sh[ch+3]));
            frag_store4(Ah, Al, r, c4, v);
        }
    }
    // B: copy interleaved hi/lo fragment image (KS16*2048 words = KS16*512 uint4)
    {
        const uint4* wp = (const uint4*)(Wf + wfbase);
        for (int i = t; i < KS16*512; i += 128)
            ((uint4*)Bc)[i] = wp[i];
    }
    __syncthreads();

    #pragma unroll
    for (int kstep = 0; kstep < KS16; kstep++) {
        uint ah[2][4], al[2][4];
        #pragma unroll
        for (int mb = 0; mb < 2; mb++) {
            int base = ((kstep*4 + (w & 1)*2 + mb)*32 + lane)*4;
            uint4 vh = *(const uint4*)&Ah[base];
            uint4 vl = *(const uint4*)&Al[base];
            ah[mb][0]=vh.x; ah[mb][1]=vh.y; ah[mb][2]=vh.z; ah[mb][3]=vh.w;
            al[mb][0]=vl.x; al[mb][1]=vl.y; al[mb][2]=vl.z; al[mb][3]=vl.w;
        }
        #pragma unroll
        for (int nf = 0; nf < 8; nf++) {
            int baseb = ((kstep*16 + (wc >> 3) + nf)*32 + lane)*4;
            uint4 bb = *(const uint4*)&Bc[baseb];
            uint bh[2] = {bb.x, bb.y};
            uint bl[2] = {bb.z, bb.w};
            #pragma unroll
            for (int mb = 0; mb < 2; mb++) {
                MMAB(acc[mb][nf], ah[mb], bh);
                MMAB(acc[mb][nf], al[mb], bh);
                MMAB(acc[mb][nf], ah[mb], bl);
            }
        }
    }
    __syncthreads();
}

// ---------------- bf16x3 GEMM: CTA 64x128, 128 thr ---------------------------
#define GSM ((12288 + 256) * 4)   // 16KB A + 32KB B + 1KB coef
template<int LAYER>
__global__ void __launch_bounds__(128, 4)
gemm_tc(const float* __restrict__ xyz,
        const float* __restrict__ gprev, const float* __restrict__ beprev,
        int otile) {
    const float* A = (LAYER == 1) ? g_y1 : g_y2;   // unused for LAYER==0
    float*       Y = (LAYER == 0) ? g_y1 : g_y2;
    const uint* Wf = (LAYER == 0) ? g_wf0 : ((LAYER == 1) ? g_wf1 : g_wf2);

    extern __shared__ uint usm[];
    uint* Ah = usm;              // 2048 words
    uint* Al = usm + 2048;
    uint* Bc = usm + 4096;       // 8192 words interleaved
    float* scs = (float*)(usm + 12288);   // 128
    float* shs = (float*)(usm + 12416);   // 128

    const int t = threadIdx.x;
    const int lane = t & 31, w = t >> 5;            // 4 warps
    const int wr = (w & 1) * 32, wc = (w >> 1) * 64;
    const size_t m0 = (size_t)blockIdx.x * 64;
    const int o0 = otile * 128;

    if (LAYER > 0) {
        float s, sh;
        bn_coef(LAYER - 1, t, gprev, beprev, s, sh);
        scs[t] = s; shs[t] = sh;
    }
    __syncthreads();

    float acc[2][8][4];
    #pragma unroll
    for (int mb = 0; mb < 2; mb++)
        #pragma unroll
        for (int nf = 0; nf < 8; nf++)
            #pragma unroll
            for (int c = 0; c < 4; c++) acc[mb][nf][c] = 0.f;

    int wb0 = (LAYER == 2) ? otile*16384 : 0;
    do_chunk<4, LAYER>(A, xyz, m0, 0, scs, shs, Wf, wb0, Ah, Al, Bc, t, lane, w, wc, acc);
    if (LAYER == 0)
        do_chunk<1, LAYER>(A, xyz, m0, 64, scs, shs, Wf, 8192, Ah, Al, Bc, t, lane, w, wc, acc);
    else
        do_chunk<4, LAYER>(A, xyz, m0, 64, scs, shs, Wf, wb0 + 8192, Ah, Al, Bc, t, lane, w, wc, acc);

    // ---- epilogue: store Y (layers 0,1) ----
    if (LAYER < 2) {
        #pragma unroll
        for (int mb = 0; mb < 2; mb++)
            #pragma unroll
            for (int h = 0; h < 2; h++) {
                size_t row = m0 + wr + mb*16 + (lane >> 2) + h*8;
                float* yr = &Y[row*128 + wc + (lane & 3)*2];
                #pragma unroll
                for (int nf = 0; nf < 8; nf++)
                    *(float2*)&yr[nf*8] = make_float2(acc[mb][nf][h*2], acc[mb][nf][h*2+1]);
            }
    }

    // ---- per-column partial stats, and max/min for LAYER 2 ----
    float csum[8][2], csq[8][2];
    #pragma unroll
    for (int nf = 0; nf < 8; nf++)
        #pragma unroll
        for (int j = 0; j < 2; j++) { csum[nf][j] = 0.f; csq[nf][j] = 0.f; }
    float cmx[8][2], cmn[8][2];
    if (LAYER == 2) {
        #pragma unroll
        for (int nf = 0; nf < 8; nf++)
            #pragma unroll
            for (int j = 0; j < 2; j++) { cmx[nf][j] = -3.4e38f; cmn[nf][j] = 3.4e38f; }
    }
    #pragma unroll
    for (int mb = 0; mb < 2; mb++)
        #pragma unroll
        for (int nf = 0; nf < 8; nf++)
            #pragma unroll
            for (int c = 0; c < 4; c++) {
                int j = c & 1;
                float v = acc[mb][nf][c];
                csum[nf][j] += v;
                csq[nf][j] = fmaf(v, v, csq[nf][j]);
                if (LAYER == 2) {
                    cmx[nf][j] = fmaxf(cmx[nf][j], v);
                    cmn[nf][j] = fminf(cmn[nf][j], v);
                }
            }

    float* red = (float*)usm;   // [2][128] reuse
    #pragma unroll
    for (int nf = 0; nf < 8; nf++)
        #pragma unroll
        for (int j = 0; j < 2; j++) {
            float v = csum[nf][j];
            #pragma unroll
            for (int o = 4; o < 32; o <<= 1) v += __shfl_xor_sync(0xffffffffu, v, o);
            if (lane < 4) red[(w & 1)*128 + wc + nf*8 + lane*2 + j] = v;
        }
    __syncthreads();
    if (t < 128) atomicAdd(&g_sum[LAYER*256 + o0 + t], red[t] + red[128 + t]);
    __syncthreads();
    #pragma unroll
    for (int nf = 0; nf < 8; nf++)
        #pragma unroll
        for (int j = 0; j < 2; j++) {
            float v = csq[nf][j];
            #pragma unroll
            for (int o = 4; o < 32; o <<= 1) v += __shfl_xor_sync(0xffffffffu, v, o);
            if (lane < 4) red[(w & 1)*128 + wc + nf*8 + lane*2 + j] = v;
        }
    __syncthreads();
    if (t < 128) atomicAdd(&g_sqs[LAYER*256 + o0 + t], red[t] + red[128 + t]);

    if (LAYER == 2) {
        __syncthreads();
        #pragma unroll
        for (int nf = 0; nf < 8; nf++)
            #pragma unroll
            for (int j = 0; j < 2; j++) {
                float v = cmx[nf][j];
                #pragma unroll
                for (int o = 4; o < 32; o <<= 1) v = fmaxf(v, __shfl_xor_sync(0xffffffffu, v, o));
                if (lane < 4) red[(w & 1)*128 + wc + nf*8 + lane*2 + j] = v;
            }
        __syncthreads();
        if (t < 128)
            g_mx[((size_t)blockIdx.x)*256 + o0 + t] = fmaxf(red[t], red[128 + t]);
        __syncthreads();
        #pragma unroll
        for (int nf = 0; nf < 8; nf++)
            #pragma unroll
            for (int j = 0; j < 2; j++) {
                float v = cmn[nf][j];
                #pragma unroll
                for (int o = 4; o < 32; o <<= 1) v = fminf(v, __shfl_xor_sync(0xffffffffu, v, o));
                if (lane < 4) red[(w & 1)*128 + wc + nf*8 + lane*2 + j] = v;
            }
        __syncthreads();
        if (t < 128)
            g_mn[((size_t)blockIdx.x)*256 + o0 + t] = fminf(red[t], red[128 + t]);
    }
}

// ---------------- final: BN3 (in-kernel coef) + relu on extremum, transpose --
__global__ void final_out_kernel(const float* __restrict__ g2,
                                 const float* __restrict__ be2,
                                 float* __restrict__ out_feat) {
    __shared__ float tile[32][33];
    int bs0 = blockIdx.x * 32, c0 = blockIdx.y * 32;
    int tx = threadIdx.x, ty = threadIdx.y;   // 32 x 8
    float s, shv;
    bn_coef(2, c0 + tx, g2, be2, s, shv);
    #pragma unroll
    for (int j = 0; j < 32; j += 8) {
        int bs = bs0 + ty + j;
        float mx = g_mx[(size_t)bs*256 + c0 + tx];
        float mn = g_mn[(size_t)bs*256 + c0 + tx];
        float e = (s >= 0.f) ? mx : mn;
        tile[ty + j][tx] = fmaxf(0.f, fmaf(s, e, shv));
    }
    __syncthreads();
    int b = bs0 >> 10, sl = bs0 & 1023;
    #pragma unroll
    for (int j = 0; j < 32; j += 8)
        out_feat[((size_t)(b*256 + c0 + ty + j))*1024 + sl + tx] = tile[tx][ty + j];
}

// ---------------- launcher ---------------------------------------------------
extern "C" void kernel_launch(void* const* d_in, const int* in_sizes, int n_in,
                              void* d_out, int out_size) {
    const float* xyz = (const float*)d_in[0];
    const float* pts = (const float*)d_in[1];
    const int*   idx = (const int*)d_in[2];
    const float* w0  = (const float*)d_in[3];
    const float* g0  = (const float*)d_in[5];
    const float* be0 = (const float*)d_in[6];
    const float* w1  = (const float*)d_in[7];
    const float* g1  = (const float*)d_in[9];
    const float* be1 = (const float*)d_in[10];
    const float* w2  = (const float*)d_in[11];
    const float* g2  = (const float*)d_in[13];
    const float* be2 = (const float*)d_in[14];

    float* out      = (float*)d_out;
    float* out_xyz  = out;                       // [B,3,SPT]
    float* out_feat = out + (size_t)B_*3*SPT;    // [B,256,SPT]

    cudaFuncSetAttribute(front_kernel, cudaFuncAttributeMaxDynamicSharedMemorySize, FPS_SMEM);
    cudaFuncSetAttribute(gemm_tc<0>, cudaFuncAttributeMaxDynamicSharedMemorySize, GSM);
    cudaFuncSetAttribute(gemm_tc<1>, cudaFuncAttributeMaxDynamicSharedMemorySize, GSM);
    cudaFuncSetAttribute(gemm_tc<2>, cudaFuncAttributeMaxDynamicSharedMemorySize, GSM);

    front_kernel<<<8 + NTRB, 512, FPS_SMEM>>>(xyz, idx, pts, w0, w1, w2, out_xyz);
    ballquery_kernel<<<(B_*SPT)/8, 256>>>();

    gemm_tc<0><<<MTOT/64, 128, GSM>>>(xyz, (const float*)0, (const float*)0, 0);
    gemm_tc<1><<<MTOT/64, 128, GSM>>>(xyz, g0, be0, 0);
    gemm_tc<2><<<MTOT/64, 128, GSM>>>(xyz, g1, be1, 0);
    gemm_tc<2><<<MTOT/64, 128, GSM>>>(xyz, g1, be1, 1);   // launch #6 -> ncu capture

    final_out_kernel<<<dim3(NGRP/32, 256/32), dim3(32, 8)>>>(g2, be2, out_feat);
}

// round 15
// speedup vs baseline: 1.1012x; 1.1012x over previous
#include <cuda_runtime.h>
#include <cuda_bf16.h>
#include <math.h>

#define B_ 8
#define NPT 16384
#define SPT 1024
#define NS 64
#define DD 64
#define C0 67
#define MTOT (B_*SPT*NS)      // 524288
#define NGRP (MTOT/NS)        // 8192
#define RR2 0.09f
#define EPSV 1e-5f

typedef unsigned long long ull;
typedef unsigned uint;

// ---------------- scratch (static device globals; no allocation) -------------
__device__ __align__(16) float g_ptsT[(size_t)B_*NPT*DD];       // 33.5 MB
__device__ __align__(16) float4 g_pk[(size_t)B_*NPT];           // 2 MB packed xyz+id
__device__ float g_newxyz[B_*SPT*3];
__device__ int   g_fpsidx[B_*SPT];
__device__ int   g_newptr[B_*SPT];
__device__ int   g_gid[B_*SPT*NS];
__device__ __align__(16) float g_y1[(size_t)MTOT*128];          // 268 MB
__device__ __align__(16) float g_y2[(size_t)MTOT*128];          // 268 MB
__device__ __align__(16) float g_mx[(size_t)NGRP*256];          // 8 MB
__device__ __align__(16) float g_mn[(size_t)NGRP*256];          // 8 MB
__device__ float g_sum[3*256];
__device__ float g_sqs[3*256];
// weights pre-split (bf16 hi/lo) packed in m16n8k16 B-fragment layout
#define W0WORDS (5*1024)      // KP=80: 5 ksteps
#define W1WORDS (8*1024)      // KP=128
#define W2WORDS (2*8*1024)    // 2 otiles
#define TOTALW (W0WORDS + W1WORDS + W2WORDS)
__device__ __align__(16) uint g_wf0h[W0WORDS], g_wf0l[W0WORDS];
__device__ __align__(16) uint g_wf1h[W1WORDS], g_wf1l[W1WORDS];
__device__ __align__(16) uint g_wf2h[W2WORDS], g_wf2l[W2WORDS];

// ---------------- f32x2 packed helpers ---------------------------------------
#define ADD2(o, a, b) asm("add.rn.f32x2 %0, %1, %2;" : "=l"(o) : "l"(a), "l"(b))
#define MUL2(o, a, b) asm("mul.rn.f32x2 %0, %1, %2;" : "=l"(o) : "l"(a), "l"(b))
#define FMA2(o, a, b, c) asm("fma.rn.f32x2 %0, %1, %2, %3;" : "=l"(o) : "l"(a), "l"(b), "l"(c))

__device__ __forceinline__ ull bcast2(float v) {
    unsigned u = __float_as_uint(v);
    return ((ull)u << 32) | (ull)u;
}
__device__ __forceinline__ float lo2(ull m) { return __uint_as_float((unsigned)m); }
__device__ __forceinline__ float hi2(ull m) { return __uint_as_float((unsigned)(m >> 32)); }

__device__ __forceinline__ uint pk_bf2(float a, float b) {
    uint r;
    asm("cvt.rn.bf16x2.f32 %0, %1, %2;" : "=r"(r) : "f"(b), "f"(a));
    return r;
}
__device__ __forceinline__ void split2(float v0, float v1, uint& wh, uint& wl) {
    wh = pk_bf2(v0, v1);
    __nv_bfloat162 h2 = *(__nv_bfloat162*)&wh;
    float h0 = __bfloat162float(h2.x), h1 = __bfloat162float(h2.y);
    wl = pk_bf2(v0 - h0, v1 - h1);
}

// BN finalize formula (gemm preamble + final_out); bit-identical both places
__device__ __forceinline__ void bn_coef(int layer, int c,
                                        const float* __restrict__ gamma,
                                        const float* __restrict__ beta,
                                        float& s, float& sh) {
    const float invM = 1.f / (float)MTOT;
    float mu  = g_sum[layer*256 + c] * invM;
    float var = g_sqs[layer*256 + c] * invM - mu*mu;
    if (var < 0.f) var = 0.f;
    s  = gamma[c] * rsqrtf(var + EPSV);
    sh = fmaf(-mu, s, beta[c]);
}

// store float4 (row r in 0..63, chunk-local col base = c4*4) into A frag smem
__device__ __forceinline__ void frag_store4(uint* Ah, uint* Al, int r, int c4, float4 v) {
    int r16 = r & 15, mb = r >> 4;
    int kk0 = (c4*4) & 15, kst = (c4*4) >> 4;
    int reg = (r16 >> 3) + ((kk0 >> 3) << 1);
    int l0  = ((r16 & 7) << 2) | ((kk0 >> 1) & 3);
    int i0  = ((kst*4 + mb)*32 + l0)*4 + reg;
    uint wh, wl;
    split2(v.x, v.y, wh, wl);
    Ah[i0] = wh; Al[i0] = wl;
    split2(v.z, v.w, wh, wl);
    Ah[i0 + 4] = wh; Al[i0 + 4] = wl;
}

// ---------------- FRONT: fps (blocks 0..7) + prep/transpose (blocks 8+) ------
#define FPS_SMEM ((3*NPT + 64) * 4)
#define NTRB 4096
__global__ void __launch_bounds__(512, 1)
front_kernel(const float* __restrict__ xyz, const int* __restrict__ idx,
             const float* __restrict__ pts,
             const float* __restrict__ w0, const float* __restrict__ w1,
             const float* __restrict__ w2,
             float* __restrict__ out_xyz) {
    extern __shared__ float fsm[];
    const int t = threadIdx.x;

    if (blockIdx.x >= 8) {
        int bid = blockIdx.x - 8;
        int gi = bid*512 + t;
        if (gi < 768) { g_sum[gi] = 0.f; g_sqs[gi] = 0.f; }
        if (gi < B_*NPT) {
            int b = gi >> 14, n = gi & (NPT-1);
            const float* px = xyz + (size_t)b*3*NPT;
            g_pk[gi] = make_float4(px[n], px[NPT+n], px[2*NPT+n], __int_as_float(idx[gi]));
        }
        if (gi < TOTALW) {
            int layer, j, otile = 0;
            if (gi < W0WORDS) { layer = 0; j = gi; }
            else if (gi < W0WORDS + W1WORDS) { layer = 1; j = gi - W0WORDS; }
            else { layer = 2; j = gi - W0WORDS - W1WORDS; otile = j >> 13; j &= 8191; }
            int reg = j & 1, ln = (j >> 1) & 31, nb = (j >> 6) & 15, ksg = j >> 10;
            int o  = otile*128 + nb*8 + (ln >> 2);
            int c0 = ksg*16 + reg*8 + (ln & 3)*2;
            float v0, v1;
            if (layer == 0) {
                int s0 = (c0   < 64) ? (c0   + 3) : (c0   - 64);
                int s1 = (c0+1 < 64) ? (c0+1 + 3) : (c0+1 - 64);
                v0 = (c0   < C0) ? w0[o*C0 + s0] : 0.f;
                v1 = (c0+1 < C0) ? w0[o*C0 + s1] : 0.f;
            } else if (layer == 1) {
                v0 = w1[o*128 + c0]; v1 = w1[o*128 + c0 + 1];
            } else {
                v0 = w2[o*128 + c0]; v1 = w2[o*128 + c0 + 1];
            }
            uint wh, wl;
            split2(v0, v1, wh, wl);
            if (layer == 0)      { g_wf0h[j] = wh; g_wf0l[j] = wl; }
            else if (layer == 1) { g_wf1h[j] = wh; g_wf1l[j] = wl; }
            else { int k2 = (otile << 13) | j; g_wf2h[k2] = wh; g_wf2l[k2] = wl; }
        }
        int tile_id = bid*2 + (t >> 8);
        int sub = t & 255, tx = sub & 31, ty = sub >> 5;   // 32 x 8
        int bx = tile_id & 511, byz = tile_id >> 9;
        int by = byz & 1, bz = byz >> 1;
        int n0 = bx * 32, c0 = by * 32;
        float* tb = fsm + (t >> 8) * 1088;
        #pragma unroll
        for (int j = 0; j < 32; j += 8)
            tb[(ty + j)*33 + tx] = pts[((size_t)bz*DD + c0 + ty + j)*NPT + n0 + tx];
        __syncthreads();
        #pragma unroll
        for (int j = 0; j < 32; j += 8)
            g_ptsT[((size_t)bz*NPT + n0 + ty + j)*DD + c0 + tx] = tb[tx*33 + ty + j];
        return;
    }

    // ===================== FPS role =====================
    float* sx = fsm;
    float* sy = sx + NPT;
    float* sz = sy + NPT;
    float* redv = sz + NPT;
    __shared__ int s_idx[2];

    const int b = blockIdx.x;
    const float* px = xyz + (size_t)b*3*NPT;
    const float* py = px + NPT;
    const float* pz = py + NPT;

    for (int n = t; n < NPT; n += 512) { sx[n]=px[n]; sy[n]=py[n]; sz[n]=pz[n]; }
    if (t == 0) s_idx[0] = 0;
    __syncthreads();

    ull xp[16], yp[16];
    float dist[32];
    #pragma unroll
    for (int i = 0; i < 16; i++) {
        int p = t + (i << 9);
        xp[i] = *(const ull*)&sx[2*p];
        yp[i] = *(const ull*)&sy[2*p];
        dist[2*i] = 1e10f; dist[2*i+1] = 1e10f;
    }

    const int lane = t & 31;
    for (int s = 0; s < SPT; s++) {
        int far = s_idx[s & 1];
        float cx = sx[far], cy = sy[far], cz = sz[far];
        if (t == 0) {
            g_fpsidx[b*SPT + s] = far;
            g_newptr[b*SPT + s] = idx[b*NPT + far];
            g_newxyz[(b*SPT + s)*3 + 0] = cx;
            g_newxyz[(b*SPT + s)*3 + 1] = cy;
            g_newxyz[(b*SPT + s)*3 + 2] = cz;
            out_xyz[(b*3 + 0)*SPT + s] = cx;
            out_xyz[(b*3 + 1)*SPT + s] = cy;
            out_xyz[(b*3 + 2)*SPT + s] = cz;
            s_idx[(s + 1) & 1] = 0x7fffffff;
        }
        if (s == SPT - 1) break;

        ull ncx = bcast2(-cx), ncy = bcast2(-cy), ncz = bcast2(-cz);
        float best = -1.f;
        #pragma unroll
        for (int i = 0; i < 16; i++) {
            int p = t + (i << 9);
            ull z2 = *(const ull*)&sz[2*p];
            ull dx2, dy2, dz2, m;
            ADD2(dx2, xp[i], ncx);
            ADD2(dy2, yp[i], ncy);
            ADD2(dz2, z2,    ncz);
            MUL2(m, dx2, dx2);
            FMA2(m, dy2, dy2, m);
            FMA2(m, dz2, dz2, m);
            float d0 = fminf(dist[2*i],   lo2(m));
            float d1 = fminf(dist[2*i+1], hi2(m));
            dist[2*i] = d0; dist[2*i+1] = d1;
            best = fmaxf(best, d0);
            best = fmaxf(best, d1);
        }
        float wmax = best;
        #pragma unroll
        for (int o = 16; o > 0; o >>= 1)
            wmax = fmaxf(wmax, __shfl_xor_sync(0xffffffffu, wmax, o));
        if (lane == 0) redv[t >> 5] = wmax;
        __syncthreads();
        float vmax = redv[lane & 15];
        #pragma unroll
        for (int o = 8; o > 0; o >>= 1)
            vmax = fmaxf(vmax, __shfl_xor_sync(0xffffffffu, vmax, o));
        if (best == vmax) {
            int found = 0x7fffffff;
            #pragma unroll
            for (int i = 0; i < 16; i++) {
                int p2 = 2*(t + (i << 9));
                if (dist[2*i]   == vmax) found = min(found, p2);
                if (dist[2*i+1] == vmax) found = min(found, p2 + 1);
            }
            atomicMin(&s_idx[(s + 1) & 1], found);
        }
        __syncthreads();
    }
}

// ---------------- ball query: one warp per (b,s), packed float4 --------------
__global__ void __launch_bounds__(256)
ballquery_kernel() {
    int warp = (blockIdx.x * blockDim.x + threadIdx.x) >> 5;
    int lane = threadIdx.x & 31;
    if (warp >= B_*SPT) return;
    int b = warp / SPT;
    float cx = g_newxyz[warp*3+0], cy = g_newxyz[warp*3+1], cz = g_newxyz[warp*3+2];
    int np = g_newptr[warp];
    float cn = cx*cx + cy*cy + cz*cz;
    const float4* pk = g_pk + (size_t)b*NPT;
    int* gout = g_gid + (size_t)warp*NS;

    int cnt = 0, first = -1;
    for (int n0 = 0; n0 < NPT && cnt < NS; n0 += 128) {
        float4 vv[4];
        #pragma unroll
        for (int sb = 0; sb < 4; sb++) vv[sb] = pk[n0 + sb*32 + lane];
        #pragma unroll
        for (int sb = 0; sb < 4; sb++) {
            int n = n0 + sb*32 + lane;
            float x = vv[sb].x, y = vv[sb].y, z = vv[sb].z;
            float pn = x*x + y*y + z*z;
            float sq = cn + pn - 2.f*(cx*x + cy*y + cz*z);
            bool hit = !(sq > RR2) && (__float_as_int(vv[sb].w) == np);
            unsigned m = __ballot_sync(0xffffffffu, hit);
            if (m) {
                if (first < 0) first = n0 + sb*32 + __ffs(m) - 1;
                int pos = cnt + __popc(m & ((1u << lane) - 1));
                if (hit && pos < NS) gout[pos] = n;
                cnt += __popc(m);
                if (cnt > NS) cnt = NS;
            }
        }
    }
    if (first < 0) { first = g_fpsidx[warp]; }
    if (cnt == 0) { if (lane == 0) gout[0] = first; cnt = 1; }
    for (int p = cnt + lane; p < NS; p += 32) gout[p] = first;
}

// ---------------- bf16 mma helpers -------------------------------------------
#define MMAB(d, a, b) asm volatile( \
    "mma.sync.aligned.m16n8k16.row.col.f32.bf16.bf16.f32 " \
    "{%0,%1,%2,%3},{%4,%5,%6,%7},{%8,%9},{%0,%1,%2,%3};\n" \
    : "+f"(d[0]), "+f"(d[1]), "+f"(d[2]), "+f"(d[3]) \
    : "r"(a[0]), "r"(a[1]), "r"(a[2]), "r"(a[3]), "r"(b[0]), "r"(b[1]))

// ---------------- one K-chunk (CTA tile 64x128, 256 threads, 8 warps) --------
template<int KS16, int LAYER>
__device__ __forceinline__ void do_chunk(
    const float* __restrict__ A, const float* __restrict__ xyz, size_t m0, int kc,
    const float* sc, const float* sh,
    const uint* __restrict__ Wfh, const uint* __restrict__ Wfl, int wfbase,
    uint* Ah, uint* Al, uint* Bh, uint* Bl,
    int t, int lane, int w, int wc, float acc[2][4][4])
{
    constexpr int KP = 128;
    constexpr int CW = KS16 * 4;

    if (LAYER == 0) {
        const int bb = (int)(m0 >> 16);
        if (KS16 == 4) {
            for (int i = t; i < 64*16; i += 256) {
                int r = i >> 4, c4 = i & 15;
                int g = g_gid[m0 + r];
                float4 v = *(const float4*)&g_ptsT[((size_t)bb*NPT + g)*DD + c4*4];
                frag_store4(Ah, Al, r, c4, v);
            }
        } else {
            const float* px = xyz + (size_t)bb*3*NPT;
            for (int i = t; i < 64*4; i += 256) {
                int r = i >> 2, c4 = i & 3;
                float4 v = make_float4(0.f, 0.f, 0.f, 0.f);
                if (c4 == 0) {
                    int g = g_gid[m0 + r];
                    int bs = (int)((m0 + r) >> 6);
                    v = make_float4(px[g]        - g_newxyz[bs*3+0],
                                    px[NPT+g]    - g_newxyz[bs*3+1],
                                    px[2*NPT+g]  - g_newxyz[bs*3+2], 0.f);
                }
                frag_store4(Ah, Al, r, c4, v);
            }
        }
    } else {
        for (int i = t; i < 64*CW; i += 256) {
            int r = i / CW, c4 = i - r*CW;
            float4 v = *(const float4*)&A[(m0 + r)*KP + kc + c4*4];
            int ch = kc + c4*4;
            v.x = fmaxf(0.f, fmaf(sc[ch+0], v.x, sh[ch+0]));
            v.y = fmaxf(0.f, fmaf(sc[ch+1], v.y, sh[ch+1]));
            v.z = fmaxf(0.f, fmaf(sc[ch+2], v.z, sh[ch+2]));
            v.w = fmaxf(0.f, fmaf(sc[ch+3], v.w, sh[ch+3]));
            frag_store4(Ah, Al, r, c4, v);
        }
    }
    {
        const uint4* shp = (const uint4*)(Wfh + wfbase);
        const uint4* slp = (const uint4*)(Wfl + wfbase);
        for (int i = t; i < KS16*256; i += 256) {
            ((uint4*)Bh)[i] = shp[i];
            ((uint4*)Bl)[i] = slp[i];
        }
    }
    __syncthreads();

    #pragma unroll
    for (int kstep = 0; kstep < KS16; kstep++) {
        uint ah[2][4], al[2][4];
        #pragma unroll
        for (int mb = 0; mb < 2; mb++) {
            int base = ((kstep*4 + (w & 1)*2 + mb)*32 + lane)*4;
            uint4 vh = *(const uint4*)&Ah[base];
            uint4 vl = *(const uint4*)&Al[base];
            ah[mb][0]=vh.x; ah[mb][1]=vh.y; ah[mb][2]=vh.z; ah[mb][3]=vh.w;
            al[mb][0]=vl.x; al[mb][1]=vl.y; al[mb][2]=vl.z; al[mb][3]=vl.w;
        }
        #pragma unroll
        for (int nf = 0; nf < 4; nf++) {
            int baseb = ((kstep*16 + (wc >> 3) + nf)*32 + lane)*2;
            uint2 bhv = *(const uint2*)&Bh[baseb];
            uint2 blv = *(const uint2*)&Bl[baseb];
            uint bh[2] = {bhv.x, bhv.y};
            uint bl[2] = {blv.x, blv.y};
            #pragma unroll
            for (int mb = 0; mb < 2; mb++) {
                MMAB(acc[mb][nf], ah[mb], bh);
                MMAB(acc[mb][nf], al[mb], bh);
                MMAB(acc[mb][nf], ah[mb], bl);
            }
        }
    }
    __syncthreads();
}

// ---------------- bf16x3 GEMM: CTA 64x128, 256 thr, warp tile 32x32 ----------
#define GSM ((12288 + 256) * 4)   // 16KB A + 32KB B + 1KB coef
template<int LAYER>
__global__ void __launch_bounds__(256, 3)
gemm_tc(const float* __restrict__ xyz,
        const float* __restrict__ gprev, const float* __restrict__ beprev,
        int otile) {
    const float* A = (LAYER == 1) ? g_y1 : g_y2;   // unused for LAYER==0
    float*       Y = (LAYER == 0) ? g_y1 : g_y2;
    const uint* Wfh = (LAYER == 0) ? g_wf0h : ((LAYER == 1) ? g_wf1h : g_wf2h);
    const uint* Wfl = (LAYER == 0) ? g_wf0l : ((LAYER == 1) ? g_wf1l : g_wf2l);

    extern __shared__ uint usm[];
    uint* Ah = usm;              // 2048 words
    uint* Al = usm + 2048;
    uint* Bh = usm + 4096;       // 4096 words
    uint* Bl = usm + 8192;
    float* scs = (float*)(usm + 12288);   // 128
    float* shs = (float*)(usm + 12416);   // 128

    const int t = threadIdx.x;
    const int lane = t & 31, w = t >> 5;            // 8 warps
    const int wr = (w & 1) * 32, wc = (w >> 1) * 32;
    const size_t m0 = (size_t)blockIdx.x * 64;
    const int o0 = otile * 128;

    if (LAYER > 0 && t < 128) {
        float s, sh;
        bn_coef(LAYER - 1, t, gprev, beprev, s, sh);
        scs[t] = s; shs[t] = sh;
    }
    __syncthreads();

    float acc[2][4][4];
    #pragma unroll
    for (int mb = 0; mb < 2; mb++)
        #pragma unroll
        for (int nf = 0; nf < 4; nf++)
            #pragma unroll
            for (int c = 0; c < 4; c++) acc[mb][nf][c] = 0.f;

    int wb0 = (LAYER == 2) ? (otile*8)*1024 : 0;
    do_chunk<4, LAYER>(A, xyz, m0, 0, scs, shs, Wfh, Wfl, wb0, Ah, Al, Bh, Bl, t, lane, w, wc, acc);
    if (LAYER == 0)
        do_chunk<1, LAYER>(A, xyz, m0, 64, scs, shs, Wfh, Wfl, 4*1024, Ah, Al, Bh, Bl, t, lane, w, wc, acc);
    else
        do_chunk<4, LAYER>(A, xyz, m0, 64, scs, shs, Wfh, Wfl, wb0 + 4*1024, Ah, Al, Bh, Bl, t, lane, w, wc, acc);

    // ---- epilogue: store Y (layers 0,1) ----
    if (LAYER < 2) {
        #pragma unroll
        for (int mb = 0; mb < 2; mb++)
            #pragma unroll
            for (int h = 0; h < 2; h++) {
                size_t row = m0 + wr + mb*16 + (lane >> 2) + h*8;
                float* yr = &Y[row*128 + wc + (lane & 3)*2];
                #pragma unroll
                for (int nf = 0; nf < 4; nf++)
                    *(float2*)&yr[nf*8] = make_float2(acc[mb][nf][h*2], acc[mb][nf][h*2+1]);
            }
    }

    // ---- per-column partial stats, and max/min for LAYER 2 ----
    float csum[4][2], csq[4][2];
    #pragma unroll
    for (int nf = 0; nf < 4; nf++)
        #pragma unroll
        for (int j = 0; j < 2; j++) { csum[nf][j] = 0.f; csq[nf][j] = 0.f; }
    float cmx[4][2], cmn[4][2];
    if (LAYER == 2) {
        #pragma unroll
        for (int nf = 0; nf < 4; nf++)
            #pragma unroll
            for (int j = 0; j < 2; j++) { cmx[nf][j] = -3.4e38f; cmn[nf][j] = 3.4e38f; }
    }
    #pragma unroll
    for (int mb = 0; mb < 2; mb++)
        #pragma unroll
        for (int nf = 0; nf < 4; nf++)
            #pragma unroll
            for (int c = 0; c < 4; c++) {
                int j = c & 1;
                float v = acc[mb][nf][c];
                csum[nf][j] += v;
                csq[nf][j] = fmaf(v, v, csq[nf][j]);
                if (LAYER == 2) {
                    cmx[nf][j] = fmaxf(cmx[nf][j], v);
                    cmn[nf][j] = fminf(cmn[nf][j], v);
                }
            }

    float* red = (float*)usm;   // [2][128] reuse
    #pragma unroll
    for (int nf = 0; nf < 4; nf++)
        #pragma unroll
        for (int j = 0; j < 2; j++) {
            float v = csum[nf][j];
            #pragma unroll
            for (int o = 4; o < 32; o <<= 1) v += __shfl_xor_sync(0xffffffffu, v, o);
            if (lane < 4) red[(w & 1)*128 + wc + nf*8 + lane*2 + j] = v;
        }
    __syncthreads();
    if (t < 128) atomicAdd(&g_sum[LAYER*256 + o0 + t], red[t] + red[128 + t]);
    __syncthreads();
    #pragma unroll
    for (int nf = 0; nf < 4; nf++)
        #pragma unroll
        for (int j = 0; j < 2; j++) {
            float v = csq[nf][j];
            #pragma unroll
            for (int o = 4; o < 32; o <<= 1) v += __shfl_xor_sync(0xffffffffu, v, o);
            if (lane < 4) red[(w & 1)*128 + wc + nf*8 + lane*2 + j] = v;
        }
    __syncthreads();
    if (t < 128) atomicAdd(&g_sqs[LAYER*256 + o0 + t], red[t] + red[128 + t]);

    if (LAYER == 2) {
        __syncthreads();
        #pragma unroll
        for (int nf = 0; nf < 4; nf++)
            #pragma unroll
            for (int j = 0; j < 2; j++) {
                float v = cmx[nf][j];
                #pragma unroll
                for (int o = 4; o < 32; o <<= 1) v = fmaxf(v, __shfl_xor_sync(0xffffffffu, v, o));
                if (lane < 4) red[(w & 1)*128 + wc + nf*8 + lane*2 + j] = v;
            }
        __syncthreads();
        if (t < 128)
            g_mx[((size_t)blockIdx.x)*256 + o0 + t] = fmaxf(red[t], red[128 + t]);
        __syncthreads();
        #pragma unroll
        for (int nf = 0; nf < 4; nf++)
            #pragma unroll
            for (int j = 0; j < 2; j++) {
                float v = cmn[nf][j];
                #pragma unroll
                for (int o = 4; o < 32; o <<= 1) v = fminf(v, __shfl_xor_sync(0xffffffffu, v, o));
                if (lane < 4) red[(w & 1)*128 + wc + nf*8 + lane*2 + j] = v;
            }
        __syncthreads();
        if (t < 128)
            g_mn[((size_t)blockIdx.x)*256 + o0 + t] = fminf(red[t], red[128 + t]);
    }
}

// ---------------- final: BN3 (in-kernel coef) + relu on extremum, transpose --
__global__ void final_out_kernel(const float* __restrict__ g2,
                                 const float* __restrict__ be2,
                                 float* __restrict__ out_feat) {
    __shared__ float tile[32][33];
    int bs0 = blockIdx.x * 32, c0 = blockIdx.y * 32;
    int tx = threadIdx.x, ty = threadIdx.y;   // 32 x 8
    float s, shv;
    bn_coef(2, c0 + tx, g2, be2, s, shv);
    #pragma unroll
    for (int j = 0; j < 32; j += 8) {
        int bs = bs0 + ty + j;
        float mx = g_mx[(size_t)bs*256 + c0 + tx];
        float mn = g_mn[(size_t)bs*256 + c0 + tx];
        float e = (s >= 0.f) ? mx : mn;
        tile[ty + j][tx] = fmaxf(0.f, fmaf(s, e, shv));
    }
    __syncthreads();
    int b = bs0 >> 10, sl = bs0 & 1023;
    #pragma unroll
    for (int j = 0; j < 32; j += 8)
        out_feat[((size_t)(b*256 + c0 + ty + j))*1024 + sl + tx] = tile[tx][ty + j];
}

// ---------------- launcher ---------------------------------------------------
extern "C" void kernel_launch(void* const* d_in, const int* in_sizes, int n_in,
                              void* d_out, int out_size) {
    const float* xyz = (const float*)d_in[0];
    const float* pts = (const float*)d_in[1];
    const int*   idx = (const int*)d_in[2];
    const float* w0  = (const float*)d_in[3];
    const float* g0  = (const float*)d_in[5];
    const float* be0 = (const float*)d_in[6];
    const float* w1  = (const float*)d_in[7];
    const float* g1  = (const float*)d_in[9];
    const float* be1 = (const float*)d_in[10];
    const float* w2  = (const float*)d_in[11];
    const float* g2  = (const float*)d_in[13];
    const float* be2 = (const float*)d_in[14];

    float* out      = (float*)d_out;
    float* out_xyz  = out;                       // [B,3,SPT]
    float* out_feat = out + (size_t)B_*3*SPT;    // [B,256,SPT]

    cudaFuncSetAttribute(front_kernel, cudaFuncAttributeMaxDynamicSharedMemorySize, FPS_SMEM);
    cudaFuncSetAttribute(gemm_tc<0>, cudaFuncAttributeMaxDynamicSharedMemorySize, GSM);
    cudaFuncSetAttribute(gemm_tc<1>, cudaFuncAttributeMaxDynamicSharedMemorySize, GSM);
    cudaFuncSetAttribute(gemm_tc<2>, cudaFuncAttributeMaxDynamicSharedMemorySize, GSM);

    front_kernel<<<8 + NTRB, 512, FPS_SMEM>>>(xyz, idx, pts, w0, w1, w2, out_xyz);
    ballquery_kernel<<<(B_*SPT)/8, 256>>>();

    gemm_tc<0><<<MTOT/64, 256, GSM>>>(xyz, (const float*)0, (const float*)0, 0);
    gemm_tc<1><<<MTOT/64, 256, GSM>>>(xyz, g0, be0, 0);
    gemm_tc<2><<<MTOT/64, 256, GSM>>>(xyz, g1, be1, 0);
    gemm_tc<2><<<MTOT/64, 256, GSM>>>(xyz, g1, be1, 1);   // launch #6 -> ncu capture

    final_out_kernel<<<dim3(NGRP/32, 256/32), dim3(32, 8)>>>(g2, be2, out_feat);
}

// round 17
// speedup vs baseline: 1.1324x; 1.0283x over previous
#include <cuda_runtime.h>
#include <cuda_bf16.h>
#include <math.h>

#define B_ 8
#define NPT 16384
#define SPT 1024
#define NS 64
#define DD 64
#define C0 67
#define MTOT (B_*SPT*NS)      // 524288
#define NGRP (MTOT/NS)        // 8192
#define RR2 0.09f
#define EPSV 1e-5f

typedef unsigned long long ull;
typedef unsigned uint;

// ---------------- scratch (static device globals; no allocation) -------------
__device__ __align__(16) float g_ptsT[(size_t)B_*NPT*DD];       // 33.5 MB
__device__ __align__(16) float4 g_pk[(size_t)B_*NPT];           // 2 MB packed xyz+id
__device__ float g_newxyz[B_*SPT*3];
__device__ int   g_fpsidx[B_*SPT];
__device__ int   g_newptr[B_*SPT];
__device__ int   g_gid[B_*SPT*NS];
__device__ __align__(16) float g_y1[(size_t)MTOT*128];          // 268 MB
__device__ __align__(16) float g_y2[(size_t)MTOT*128];          // 268 MB
__device__ __align__(16) float g_mx[(size_t)NGRP*256];          // 8 MB
__device__ __align__(16) float g_mn[(size_t)NGRP*256];          // 8 MB
__device__ float g_sum[3*256];
__device__ float g_sqs[3*256];
// weights bf16 hi/lo, row-major ldmatrix image:
// word j = kstep_g*1024 + nf*64 + h*32 + n*4 + kw  (kw = k-pair within 8-k half)
#define W0WORDS (5*1024)      // 5 global ksteps (K padded to 80)
#define W1WORDS (8*1024)
#define W2WORDS (2*8*1024)    // 2 otiles
#define TOTALW (W0WORDS + W1WORDS + W2WORDS)
__device__ __align__(16) uint g_wf0h[W0WORDS], g_wf0l[W0WORDS];
__device__ __align__(16) uint g_wf1h[W1WORDS], g_wf1l[W1WORDS];
__device__ __align__(16) uint g_wf2h[W2WORDS], g_wf2l[W2WORDS];

// ---------------- f32x2 packed helpers ---------------------------------------
#define ADD2(o, a, b) asm("add.rn.f32x2 %0, %1, %2;" : "=l"(o) : "l"(a), "l"(b))
#define MUL2(o, a, b) asm("mul.rn.f32x2 %0, %1, %2;" : "=l"(o) : "l"(a), "l"(b))
#define FMA2(o, a, b, c) asm("fma.rn.f32x2 %0, %1, %2, %3;" : "=l"(o) : "l"(a), "l"(b), "l"(c))

__device__ __forceinline__ ull bcast2(float v) {
    unsigned u = __float_as_uint(v);
    return ((ull)u << 32) | (ull)u;
}
__device__ __forceinline__ float lo2(ull m) { return __uint_as_float((unsigned)m); }
__device__ __forceinline__ float hi2(ull m) { return __uint_as_float((unsigned)(m >> 32)); }

__device__ __forceinline__ uint pk_bf2(float a, float b) {
    uint r;
    asm("cvt.rn.bf16x2.f32 %0, %1, %2;" : "=r"(r) : "f"(b), "f"(a));
    return r;
}
__device__ __forceinline__ void split2(float v0, float v1, uint& wh, uint& wl) {
    wh = pk_bf2(v0, v1);
    __nv_bfloat162 h2 = *(__nv_bfloat162*)&wh;
    float h0 = __bfloat162float(h2.x), h1 = __bfloat162float(h2.y);
    wl = pk_bf2(v0 - h0, v1 - h1);
}

// BN finalize formula (gemm preamble + final_out); bit-identical both places
__device__ __forceinline__ void bn_coef(int layer, int c,
                                        const float* __restrict__ gamma,
                                        const float* __restrict__ beta,
                                        float& s, float& sh) {
    const float invM = 1.f / (float)MTOT;
    float mu  = g_sum[layer*256 + c] * invM;
    float var = g_sqs[layer*256 + c] * invM - mu*mu;
    if (var < 0.f) var = 0.f;
    s  = gamma[c] * rsqrtf(var + EPSV);
    sh = fmaf(-mu, s, beta[c]);
}

// ---------------- FRONT: fps (blocks 0..7) + prep/transpose (blocks 8+) ------
#define FPS_SMEM ((3*NPT + 64) * 4)
#define NTRB 4096
__global__ void __launch_bounds__(512, 1)
front_kernel(const float* __restrict__ xyz, const int* __restrict__ idx,
             const float* __restrict__ pts,
             const float* __restrict__ w0, const float* __restrict__ w1,
             const float* __restrict__ w2,
             float* __restrict__ out_xyz) {
    extern __shared__ float fsm[];
    const int t = threadIdx.x;

    if (blockIdx.x >= 8) {
        int bid = blockIdx.x - 8;
        int gi = bid*512 + t;
        if (gi < 768) { g_sum[gi] = 0.f; g_sqs[gi] = 0.f; }
        if (gi < B_*NPT) {
            int b = gi >> 14, n = gi & (NPT-1);
            const float* px = xyz + (size_t)b*3*NPT;
            g_pk[gi] = make_float4(px[n], px[NPT+n], px[2*NPT+n], __int_as_float(idx[gi]));
        }
        if (gi < TOTALW) {
            int layer, j, otile = 0;
            if (gi < W0WORDS) { layer = 0; j = gi; }
            else if (gi < W0WORDS + W1WORDS) { layer = 1; j = gi - W0WORDS; }
            else { layer = 2; j = gi - W0WORDS - W1WORDS; otile = j >> 13; j &= 8191; }
            // row-major ldmatrix image decomposition
            int kw = j & 3, n = (j >> 2) & 7, h = (j >> 5) & 1;
            int nf = (j >> 6) & 15, kg = j >> 10;
            int o = otile*128 + nf*8 + n;
            int c0 = kg*16 + h*8 + kw*2;
            float v0, v1;
            if (layer == 0) {
                int s0 = (c0   < 64) ? (c0   + 3) : (c0   - 64);
                int s1 = (c0+1 < 64) ? (c0+1 + 3) : (c0+1 - 64);
                v0 = (c0   < C0) ? w0[o*C0 + s0] : 0.f;
                v1 = (c0+1 < C0) ? w0[o*C0 + s1] : 0.f;
            } else if (layer == 1) {
                v0 = w1[o*128 + c0]; v1 = w1[o*128 + c0 + 1];
            } else {
                v0 = w2[o*128 + c0]; v1 = w2[o*128 + c0 + 1];
            }
            uint wh, wl;
            split2(v0, v1, wh, wl);
            if (layer == 0)      { g_wf0h[j] = wh; g_wf0l[j] = wl; }
            else if (layer == 1) { g_wf1h[j] = wh; g_wf1l[j] = wl; }
            else { int k2 = (otile << 13) | j; g_wf2h[k2] = wh; g_wf2l[k2] = wl; }
        }
        int tile_id = bid*2 + (t >> 8);
        int sub = t & 255, tx = sub & 31, ty = sub >> 5;   // 32 x 8
        int bx = tile_id & 511, byz = tile_id >> 9;
        int by = byz & 1, bz = byz >> 1;
        int n0 = bx * 32, c0 = by * 32;
        float* tb = fsm + (t >> 8) * 1088;
        #pragma unroll
        for (int j = 0; j < 32; j += 8)
            tb[(ty + j)*33 + tx] = pts[((size_t)bz*DD + c0 + ty + j)*NPT + n0 + tx];
        __syncthreads();
        #pragma unroll
        for (int j = 0; j < 32; j += 8)
            g_ptsT[((size_t)bz*NPT + n0 + ty + j)*DD + c0 + tx] = tb[tx*33 + ty + j];
        return;
    }

    // ===================== FPS role =====================
    float* sx = fsm;
    float* sy = sx + NPT;
    float* sz = sy + NPT;
    float* redv = sz + NPT;
    __shared__ int s_idx[2];

    const int b = blockIdx.x;
    const float* px = xyz + (size_t)b*3*NPT;
    const float* py = px + NPT;
    const float* pz = py + NPT;

    for (int n = t; n < NPT; n += 512) { sx[n]=px[n]; sy[n]=py[n]; sz[n]=pz[n]; }
    if (t == 0) s_idx[0] = 0;
    __syncthreads();

    ull xp[16], yp[16];
    float dist[32];
    #pragma unroll
    for (int i = 0; i < 16; i++) {
        int p = t + (i << 9);
        xp[i] = *(const ull*)&sx[2*p];
        yp[i] = *(const ull*)&sy[2*p];
        dist[2*i] = 1e10f; dist[2*i+1] = 1e10f;
    }

    const int lane = t & 31;
    for (int s = 0; s < SPT; s++) {
        int far = s_idx[s & 1];
        float cx = sx[far], cy = sy[far], cz = sz[far];
        if (t == 0) {
            g_fpsidx[b*SPT + s] = far;
            g_newptr[b*SPT + s] = idx[b*NPT + far];
            g_newxyz[(b*SPT + s)*3 + 0] = cx;
            g_newxyz[(b*SPT + s)*3 + 1] = cy;
            g_newxyz[(b*SPT + s)*3 + 2] = cz;
            out_xyz[(b*3 + 0)*SPT + s] = cx;
            out_xyz[(b*3 + 1)*SPT + s] = cy;
            out_xyz[(b*3 + 2)*SPT + s] = cz;
            s_idx[(s + 1) & 1] = 0x7fffffff;
        }
        if (s == SPT - 1) break;

        ull ncx = bcast2(-cx), ncy = bcast2(-cy), ncz = bcast2(-cz);
        float best = -1.f;
        #pragma unroll
        for (int i = 0; i < 16; i++) {
            int p = t + (i << 9);
            ull z2 = *(const ull*)&sz[2*p];
            ull dx2, dy2, dz2, m;
            ADD2(dx2, xp[i], ncx);
            ADD2(dy2, yp[i], ncy);
            ADD2(dz2, z2,    ncz);
            MUL2(m, dx2, dx2);
            FMA2(m, dy2, dy2, m);
            FMA2(m, dz2, dz2, m);
            float d0 = fminf(dist[2*i],   lo2(m));
            float d1 = fminf(dist[2*i+1], hi2(m));
            dist[2*i] = d0; dist[2*i+1] = d1;
            best = fmaxf(best, d0);
            best = fmaxf(best, d1);
        }
        float wmax = best;
        #pragma unroll
        for (int o = 16; o > 0; o >>= 1)
            wmax = fmaxf(wmax, __shfl_xor_sync(0xffffffffu, wmax, o));
        if (lane == 0) redv[t >> 5] = wmax;
        __syncthreads();
        float vmax = redv[lane & 15];
        #pragma unroll
        for (int o = 8; o > 0; o >>= 1)
            vmax = fmaxf(vmax, __shfl_xor_sync(0xffffffffu, vmax, o));
        if (best == vmax) {
            int found = 0x7fffffff;
            #pragma unroll
            for (int i = 0; i < 16; i++) {
                int p2 = 2*(t + (i << 9));
                if (dist[2*i]   == vmax) found = min(found, p2);
                if (dist[2*i+1] == vmax) found = min(found, p2 + 1);
            }
            atomicMin(&s_idx[(s + 1) & 1], found);
        }
        __syncthreads();
    }
}

// ---------------- ball query: one warp per (b,s), packed float4 --------------
__global__ void __launch_bounds__(256)
ballquery_kernel() {
    int warp = (blockIdx.x * blockDim.x + threadIdx.x) >> 5;
    int lane = threadIdx.x & 31;
    if (warp >= B_*SPT) return;
    int b = warp / SPT;
    float cx = g_newxyz[warp*3+0], cy = g_newxyz[warp*3+1], cz = g_newxyz[warp*3+2];
    int np = g_newptr[warp];
    float cn = cx*cx + cy*cy + cz*cz;
    const float4* pk = g_pk + (size_t)b*NPT;
    int* gout = g_gid + (size_t)warp*NS;

    int cnt = 0, first = -1;
    for (int n0 = 0; n0 < NPT && cnt < NS; n0 += 128) {
        float4 vv[4];
        #pragma unroll
        for (int sb = 0; sb < 4; sb++) vv[sb] = pk[n0 + sb*32 + lane];
        #pragma unroll
        for (int sb = 0; sb < 4; sb++) {
            int n = n0 + sb*32 + lane;
            float x = vv[sb].x, y = vv[sb].y, z = vv[sb].z;
            float pn = x*x + y*y + z*z;
            float sq = cn + pn - 2.f*(cx*x + cy*y + cz*z);
            bool hit = !(sq > RR2) && (__float_as_int(vv[sb].w) == np);
            unsigned m = __ballot_sync(0xffffffffu, hit);
            if (m) {
                if (first < 0) first = n0 + sb*32 + __ffs(m) - 1;
                int pos = cnt + __popc(m & ((1u << lane) - 1));
                if (hit && pos < NS) gout[pos] = n;
                cnt += __popc(m);
                if (cnt > NS) cnt = NS;
            }
        }
    }
    if (first < 0) { first = g_fpsidx[warp]; }
    if (cnt == 0) { if (lane == 0) gout[0] = first; cnt = 1; }
    for (int p = cnt + lane; p < NS; p += 32) gout[p] = first;
}

// ---------------- mma / ldmatrix helpers -------------------------------------
#define MMAB(d, a, b) asm volatile( \
    "mma.sync.aligned.m16n8k16.row.col.f32.bf16.bf16.f32 " \
    "{%0,%1,%2,%3},{%4,%5,%6,%7},{%8,%9},{%0,%1,%2,%3};\n" \
    : "+f"(d[0]), "+f"(d[1]), "+f"(d[2]), "+f"(d[3]) \
    : "r"(a[0]), "r"(a[1]), "r"(a[2]), "r"(a[3]), "r"(b[0]), "r"(b[1]))

#define LDSM4(r, a) asm volatile( \
    "ldmatrix.sync.aligned.m8n8.x4.shared.b16 {%0,%1,%2,%3}, [%4];" \
    : "=r"((r)[0]), "=r"((r)[1]), "=r"((r)[2]), "=r"((r)[3]) : "r"(a))

// A tile: 64 rows x 36 words (32 data + 4 pad) per hi/lo
#define AROW 36

// ---------------- one K-chunk (CTA tile 64x128, 256 threads, 8 warps) --------
template<int KS16, int LAYER>
__device__ __forceinline__ void do_chunk(
    const float* __restrict__ A, const float* __restrict__ xyz, size_t m0, int kc,
    const float* sc, const float* sh,
    const uint* __restrict__ Wfh, const uint* __restrict__ Wfl, int wfbase,
    uint* Ah2, uint* Al2, uint* Bh, uint* Bl,
    int t, const uint aAH[2], const uint aAL[2], const uint bAH[2], const uint bAL[2],
    float acc[2][4][4])
{
    constexpr int KP = 128;
    constexpr int CW = KS16 * 4;

    if (LAYER == 0) {
        const int bb = (int)(m0 >> 16);
        if (KS16 == 4) {
            for (int i = t; i < 64*16; i += 256) {
                int r = i >> 4, c4 = i & 15;
                int g = g_gid[m0 + r];
                float4 v = *(const float4*)&g_ptsT[((size_t)bb*NPT + g)*DD + c4*4];
                uint wh0, wl0, wh1, wl1;
                split2(v.x, v.y, wh0, wl0);
                split2(v.z, v.w, wh1, wl1);
                int wi = r*AROW + c4*2;
                *(uint2*)&Ah2[wi] = make_uint2(wh0, wh1);
                *(uint2*)&Al2[wi] = make_uint2(wl0, wl1);
            }
        } else {
            const float* px = xyz + (size_t)bb*3*NPT;
            for (int i = t; i < 64*4; i += 256) {
                int r = i >> 2, c4 = i & 3;
                float4 v = make_float4(0.f, 0.f, 0.f, 0.f);
                if (c4 == 0) {
                    int g = g_gid[m0 + r];
                    int bs = (int)((m0 + r) >> 6);
                    v = make_float4(px[g]        - g_newxyz[bs*3+0],
                                    px[NPT+g]    - g_newxyz[bs*3+1],
                                    px[2*NPT+g]  - g_newxyz[bs*3+2], 0.f);
                }
                uint wh0, wl0, wh1, wl1;
                split2(v.x, v.y, wh0, wl0);
                split2(v.z, v.w, wh1, wl1);
                int wi = r*AROW + c4*2;
                *(uint2*)&Ah2[wi] = make_uint2(wh0, wh1);
                *(uint2*)&Al2[wi] = make_uint2(wl0, wl1);
            }
        }
    } else {
        for (int i = t; i < 64*CW; i += 256) {
            int r = i / CW, c4 = i - r*CW;
            float4 v = *(const float4*)&A[(m0 + r)*KP + kc + c4*4];
            int ch = kc + c4*4;
            v.x = fmaxf(0.f, fmaf(sc[ch+0], v.x, sh[ch+0]));
            v.y = fmaxf(0.f, fmaf(sc[ch+1], v.y, sh[ch+1]));
            v.z = fmaxf(0.f, fmaf(sc[ch+2], v.z, sh[ch+2]));
            v.w = fmaxf(0.f, fmaf(sc[ch+3], v.w, sh[ch+3]));
            uint wh0, wl0, wh1, wl1;
            split2(v.x, v.y, wh0, wl0);
            split2(v.z, v.w, wh1, wl1);
            int wi = r*AROW + c4*2;
            *(uint2*)&Ah2[wi] = make_uint2(wh0, wh1);
            *(uint2*)&Al2[wi] = make_uint2(wl0, wl1);
        }
    }
    // B: bulk copy of row-major ldmatrix image (KS16*1024 words each hi/lo)
    {
        const uint4* shp = (const uint4*)(Wfh + wfbase);
        const uint4* slp = (const uint4*)(Wfl + wfbase);
        for (int i = t; i < KS16*256; i += 256) {
            ((uint4*)Bh)[i] = shp[i];
            ((uint4*)Bl)[i] = slp[i];
        }
    }
    __syncthreads();

    #pragma unroll
    for (int kstep = 0; kstep < KS16; kstep++) {
        uint ah[2][4], al[2][4];
        #pragma unroll
        for (int mb = 0; mb < 2; mb++) {
            LDSM4(ah[mb], aAH[mb] + kstep*32);
            LDSM4(al[mb], aAL[mb] + kstep*32);
        }
        #pragma unroll
        for (int p = 0; p < 2; p++) {
            uint b4h[4], b4l[4];
            LDSM4(b4h, bAH[p] + kstep*4096);
            LDSM4(b4l, bAL[p] + kstep*4096);
            #pragma unroll
            for (int q = 0; q < 2; q++) {
                int nf = p*2 + q;
                uint bh[2] = {b4h[2*q], b4h[2*q+1]};
                uint bl[2] = {b4l[2*q], b4l[2*q+1]};
                #pragma unroll
                for (int mb = 0; mb < 2; mb++) {
                    MMAB(acc[mb][nf], ah[mb], bh);
                    MMAB(acc[mb][nf], al[mb], bh);
                    MMAB(acc[mb][nf], ah[mb], bl);
                }
            }
        }
    }
    __syncthreads();
}

// ---------------- bf16x3 GEMM: CTA 64x128, 256 thr, warp tile 32x32 ----------
// smem words: Ah2 2304 | Al2 2304 | Bh 4096 | Bl 4096 | coef 256 = 13056
#define GSM (13056 * 4)
template<int LAYER>
__global__ void __launch_bounds__(256, 3)
gemm_tc(const float* __restrict__ xyz,
        const float* __restrict__ gprev, const float* __restrict__ beprev,
        int otile) {
    const float* A = (LAYER == 1) ? g_y1 : g_y2;   // unused for LAYER==0
    float*       Y = (LAYER == 0) ? g_y1 : g_y2;
    const uint* Wfh = (LAYER == 0) ? g_wf0h : ((LAYER == 1) ? g_wf1h : g_wf2h);
    const uint* Wfl = (LAYER == 0) ? g_wf0l : ((LAYER == 1) ? g_wf1l : g_wf2l);

    extern __shared__ uint usm[];
    uint* Ah2 = usm;             // 2304 words
    uint* Al2 = usm + 2304;
    uint* Bh  = usm + 4608;      // 4096 words
    uint* Bl  = usm + 8704;
    float* scs = (float*)(usm + 12800);   // 128
    float* shs = (float*)(usm + 12928);   // 128

    const int t = threadIdx.x;
    const int lane = t & 31, w = t >> 5;            // 8 warps
    const int wr = (w & 1) * 32, wc = (w >> 1) * 32;
    const size_t m0 = (size_t)blockIdx.x * 64;
    const int o0 = otile * 128;

    if (LAYER > 0 && t < 128) {
        float s, sh;
        bn_coef(LAYER - 1, t, gprev, beprev, s, sh);
        scs[t] = s; shs[t] = sh;
    }
    __syncthreads();

    // ldmatrix per-lane base addresses (byte, shared space)
    const uint AhS = (uint)__cvta_generic_to_shared(Ah2);
    const uint AlS = (uint)__cvta_generic_to_shared(Al2);
    const uint BhS = (uint)__cvta_generic_to_shared(Bh);
    const uint BlS = (uint)__cvta_generic_to_shared(Bl);
    uint aAH[2], aAL[2], bAH[2], bAL[2];
    {
        int arow0 = wr + (lane & 15);
        uint aoff = (uint)(arow0*(AROW*4) + ((lane >> 4) << 4));  // row*144 + (lane>>4)*16
        aAH[0] = AhS + aoff;            aAL[0] = AlS + aoff;
        aAH[1] = AhS + aoff + 16*AROW*4; aAL[1] = AlS + aoff + 16*AROW*4;
        int nfb = wc >> 3, h = (lane >> 3) & 1, n = lane & 7;
        #pragma unroll
        for (int p = 0; p < 2; p++) {
            int nf_l = nfb + p*2 + (lane >> 4);
            uint boff = (uint)(((nf_l*2 + h)*8 + n)*16);
            bAH[p] = BhS + boff;
            bAL[p] = BlS + boff;
        }
    }

    float acc[2][4][4];
    #pragma unroll
    for (int mb = 0; mb < 2; mb++)
        #pragma unroll
        for (int nf = 0; nf < 4; nf++)
            #pragma unroll
            for (int c = 0; c < 4; c++) acc[mb][nf][c] = 0.f;

    int wb0 = (LAYER == 2) ? (otile*8)*1024 : 0;
    do_chunk<4, LAYER>(A, xyz, m0, 0, scs, shs, Wfh, Wfl, wb0, Ah2, Al2, Bh, Bl, t, aAH, aAL, bAH, bAL, acc);
    if (LAYER == 0)
        do_chunk<1, LAYER>(A, xyz, m0, 64, scs, shs, Wfh, Wfl, 4*1024, Ah2, Al2, Bh, Bl, t, aAH, aAL, bAH, bAL, acc);
    else
        do_chunk<4, LAYER>(A, xyz, m0, 64, scs, shs, Wfh, Wfl, wb0 + 4*1024, Ah2, Al2, Bh, Bl, t, aAH, aAL, bAH, bAL, acc);

    // ---- epilogue: store Y (layers 0,1) ----
    if (LAYER < 2) {
        #pragma unroll
        for (int mb = 0; mb < 2; mb++)
            #pragma unroll
            for (int h = 0; h < 2; h++) {
                size_t row = m0 + wr + mb*16 + (lane >> 2) + h*8;
                float* yr = &Y[row*128 + wc + (lane & 3)*2];
                #pragma unroll
                for (int nf = 0; nf < 4; nf++)
                    *(float2*)&yr[nf*8] = make_float2(acc[mb][nf][h*2], acc[mb][nf][h*2+1]);
            }
    }

    // ---- per-column partial stats, and max/min for LAYER 2 ----
    float csum[4][2], csq[4][2];
    #pragma unroll
    for (int nf = 0; nf < 4; nf++)
        #pragma unroll
        for (int j = 0; j < 2; j++) { csum[nf][j] = 0.f; csq[nf][j] = 0.f; }
    float cmx[4][2], cmn[4][2];
    if (LAYER == 2) {
        #pragma unroll
        for (int nf = 0; nf < 4; nf++)
            #pragma unroll
            for (int j = 0; j < 2; j++) { cmx[nf][j] = -3.4e38f; cmn[nf][j] = 3.4e38f; }
    }
    #pragma unroll
    for (int mb = 0; mb < 2; mb++)
        #pragma unroll
        for (int nf = 0; nf < 4; nf++)
            #pragma unroll
            for (int c = 0; c < 4; c++) {
                int j = c & 1;
                float v = acc[mb][nf][c];
                csum[nf][j] += v;
                csq[nf][j] = fmaf(v, v, csq[nf][j]);
                if (LAYER == 2) {
                    cmx[nf][j] = fmaxf(cmx[nf][j], v);
                    cmn[nf][j] = fminf(cmn[nf][j], v);
                }
            }

    float* red = (float*)usm;   // [2][128] reuse
    #pragma unroll
    for (int nf = 0; nf < 4; nf++)
        #pragma unroll
        for (int j = 0; j < 2; j++) {
            float v = csum[nf][j];
            #pragma unroll
            for (int o = 4; o < 32; o <<= 1) v += __shfl_xor_sync(0xffffffffu, v, o);
            if (lane < 4) red[(w & 1)*128 + wc + nf*8 + lane*2 + j] = v;
        }
    __syncthreads();
    if (t < 128) atomicAdd(&g_sum[LAYER*256 + o0 + t], red[t] + red[128 + t]);
    __syncthreads();
    #pragma unroll
    for (int nf = 0; nf < 4; nf++)
        #pragma unroll
        for (int j = 0; j < 2; j++) {
            float v = csq[nf][j];
            #pragma unroll
            for (int o = 4; o < 32; o <<= 1) v += __shfl_xor_sync(0xffffffffu, v, o);
            if (lane < 4) red[(w & 1)*128 + wc + nf*8 + lane*2 + j] = v;
        }
    __syncthreads();
    if (t < 128) atomicAdd(&g_sqs[LAYER*256 + o0 + t], red[t] + red[128 + t]);

    if (LAYER == 2) {
        __syncthreads();
        #pragma unroll
        for (int nf = 0; nf < 4; nf++)
            #pragma unroll
            for (int j = 0; j < 2; j++) {
                float v = cmx[nf][j];
                #pragma unroll
                for (int o = 4; o < 32; o <<= 1) v = fmaxf(v, __shfl_xor_sync(0xffffffffu, v, o));
                if (lane < 4) red[(w & 1)*128 + wc + nf*8 + lane*2 + j] = v;
            }
        __syncthreads();
        if (t < 128)
            g_mx[((size_t)blockIdx.x)*256 + o0 + t] = fmaxf(red[t], red[128 + t]);
        __syncthreads();
        #pragma unroll
        for (int nf = 0; nf < 4; nf++)
            #pragma unroll
            for (int j = 0; j < 2; j++) {
                float v = cmn[nf][j];
                #pragma unroll
                for (int o = 4; o < 32; o <<= 1) v = fminf(v, __shfl_xor_sync(0xffffffffu, v, o));
                if (lane < 4) red[(w & 1)*128 + wc + nf*8 + lane*2 + j] = v;
            }
        __syncthreads();
        if (t < 128)
            g_mn[((size_t)blockIdx.x)*256 + o0 + t] = fminf(red[t], red[128 + t]);
    }
}

// ---------------- final: BN3 (in-kernel coef) + relu on extremum, transpose --
__global__ void final_out_kernel(const float* __restrict__ g2,
                                 const float* __restrict__ be2,
                                 float* __restrict__ out_feat) {
    __shared__ float tile[32][33];
    int bs0 = blockIdx.x * 32, c0 = blockIdx.y * 32;
    int tx = threadIdx.x, ty = threadIdx.y;   // 32 x 8
    float s, shv;
    bn_coef(2, c0 + tx, g2, be2, s, shv);
    #pragma unroll
    for (int j = 0; j < 32; j += 8) {
        int bs = bs0 + ty + j;
        float mx = g_mx[(size_t)bs*256 + c0 + tx];
        float mn = g_mn[(size_t)bs*256 + c0 + tx];
        float e = (s >= 0.f) ? mx : mn;
        tile[ty + j][tx] = fmaxf(0.f, fmaf(s, e, shv));
    }
    __syncthreads();
    int b = bs0 >> 10, sl = bs0 & 1023;
    #pragma unroll
    for (int j = 0; j < 32; j += 8)
        out_feat[((size_t)(b*256 + c0 + ty + j))*1024 + sl + tx] = tile[tx][ty + j];
}

// ---------------- launcher ---------------------------------------------------
extern "C" void kernel_launch(void* const* d_in, const int* in_sizes, int n_in,
                              void* d_out, int out_size) {
    const float* xyz = (const float*)d_in[0];
    const float* pts = (const float*)d_in[1];
    const int*   idx = (const int*)d_in[2];
    const float* w0  = (const float*)d_in[3];
    const float* g0  = (const float*)d_in[5];
    const float* be0 = (const float*)d_in[6];
    const float* w1  = (const float*)d_in[7];
    const float* g1  = (const float*)d_in[9];
    const float* be1 = (const float*)d_in[10];
    const float* w2  = (const float*)d_in[11];
    const float* g2  = (const float*)d_in[13];
    const float* be2 = (const float*)d_in[14];

    float* out      = (float*)d_out;
    float* out_xyz  = out;                       // [B,3,SPT]
    float* out_feat = out + (size_t)B_*3*SPT;    // [B,256,SPT]

    cudaFuncSetAttribute(front_kernel, cudaFuncAttributeMaxDynamicSharedMemorySize, FPS_SMEM);
    cudaFuncSetAttribute(gemm_tc<0>, cudaFuncAttributeMaxDynamicSharedMemorySize, GSM);
    cudaFuncSetAttribute(gemm_tc<1>, cudaFuncAttributeMaxDynamicSharedMemorySize, GSM);
    cudaFuncSetAttribute(gemm_tc<2>, cudaFuncAttributeMaxDynamicSharedMemorySize, GSM);

    front_kernel<<<8 + NTRB, 512, FPS_SMEM>>>(xyz, idx, pts, w0, w1, w2, out_xyz);
    ballquery_kernel<<<(B_*SPT)/8, 256>>>();

    gemm_tc<0><<<MTOT/64, 256, GSM>>>(xyz, (const float*)0, (const float*)0, 0);
    gemm_tc<1><<<MTOT/64, 256, GSM>>>(xyz, g0, be0, 0);
    gemm_tc<2><<<MTOT/64, 256, GSM>>>(xyz, g1, be1, 0);
    gemm_tc<2><<<MTOT/64, 256, GSM>>>(xyz, g1, be1, 1);   // launch #6 -> ncu capture

    final_out_kernel<<<dim3(NGRP/32, 256/32), dim3(32, 8)>>>(g2, be2, out_feat);
}